// round 3
// baseline (speedup 1.0000x reference)
#include <cuda_runtime.h>
#include <math.h>

// Problem constants
#define BB   2
#define TT   2048
#define CC   2048
#define NH_  16
#define HS_  128
#define NLQ_ 512
#define NLKV_ 512
#define DHR_ 64

// ---------------- scratch buffers (static device allocations) ----------------
__device__ __align__(16) float d_cq  [(size_t)BB*TT*NLQ_];          //  8 MB
__device__ __align__(16) float d_ckv [(size_t)BB*TT*NLKV_];         //  8 MB
__device__ __align__(16) float d_keff[(size_t)NH_*NLQ_*NLKV_];      // 16 MB
__device__ __align__(16) float d_vtmp[(size_t)NLKV_*CC];            //  4 MB
__device__ __align__(16) float d_qlat[(size_t)BB*NH_*TT*NLKV_];     // 128 MB
__device__ __align__(16) float d_qr  [(size_t)BB*TT*NH_*DHR_];      // 16 MB
__device__ __align__(16) float d_kr  [(size_t)BB*TT*DHR_];          //  1 MB
__device__ __align__(16) float d_ctx [(size_t)BB*NH_*TT*NLKV_];     // 128 MB

// ---------------- generic strided SGEMM ----------------
// C[z][m][n] = sum_k A[m*sAm + k*sAk] * B[n*sBn + k*sBk]
// z = b*H + h ; per-operand batch offsets via (sXb, sXh).
__global__ __launch_bounds__(256) void sgemm_g(
    const float* __restrict__ A, const float* __restrict__ B, float* __restrict__ C,
    int M, int N, int K,
    long long sAm, long long sAk, long long sAb, long long sAh,
    long long sBn, long long sBk, long long sBb, long long sBh,
    long long sCm, long long sCb, long long sCh, int H)
{
    __shared__ float As[16][68];
    __shared__ float Bs[16][68];

    int z = blockIdx.z;
    int bb = z / H, hh = z - bb * H;
    A += (size_t)bb * sAb + (size_t)hh * sAh;
    B += (size_t)bb * sBb + (size_t)hh * sBh;
    C += (size_t)bb * sCb + (size_t)hh * sCh;

    int m0 = blockIdx.y * 64, n0 = blockIdx.x * 64;
    int tid = threadIdx.x;
    int tx = tid & 15, ty = tid >> 4;

    float acc[4][4];
#pragma unroll
    for (int i = 0; i < 4; i++)
#pragma unroll
        for (int j = 0; j < 4; j++) acc[i][j] = 0.f;

    for (int k0 = 0; k0 < K; k0 += 16) {
#pragma unroll
        for (int u = 0; u < 4; u++) {
            int idx = tid * 4 + u;          // 0..1023
            int m = idx >> 4, kk = idx & 15;
            int gm = m0 + m, gk = k0 + kk;
            As[kk][m] = (gm < M && gk < K) ? A[(size_t)gm * sAm + (size_t)gk * sAk] : 0.f;
            int gn = n0 + m;
            Bs[kk][m] = (gn < N && gk < K) ? B[(size_t)gn * sBn + (size_t)gk * sBk] : 0.f;
        }
        __syncthreads();
#pragma unroll
        for (int kk = 0; kk < 16; kk++) {
            float4 av = *(const float4*)&As[kk][ty << 2];
            float4 bv = *(const float4*)&Bs[kk][tx << 2];
            float a[4] = {av.x, av.y, av.z, av.w};
            float b[4] = {bv.x, bv.y, bv.z, bv.w};
#pragma unroll
            for (int i = 0; i < 4; i++)
#pragma unroll
                for (int j = 0; j < 4; j++)
                    acc[i][j] = fmaf(a[i], b[j], acc[i][j]);
        }
        __syncthreads();
    }
#pragma unroll
    for (int i = 0; i < 4; i++) {
        int gm = m0 + (ty << 2) + i;
        if (gm >= M) continue;
#pragma unroll
        for (int j = 0; j < 4; j++) {
            int gn = n0 + (tx << 2) + j;
            if (gn < N) C[(size_t)gm * sCm + gn] = acc[i][j];
        }
    }
}

// ---------------- RoPE kernels (in-place) ----------------
__global__ void rope_qr_kernel(float* __restrict__ qr,
                               const float* __restrict__ cs, const float* __restrict__ sn)
{
    int idx = blockIdx.x * blockDim.x + threadIdx.x;     // over B*T*NH*32 pairs
    if (idx >= BB * TT * NH_ * 32) return;
    int i  = idx & 31;
    int h  = (idx >> 5) & 15;
    int bt = idx >> 9;
    int t  = bt & (TT - 1);
    float c = cs[t * 32 + i], s = sn[t * 32 + i];
    size_t base = (size_t)bt * (NH_ * DHR_) + h * DHR_ + 2 * i;
    float re = qr[base], im = qr[base + 1];
    qr[base]     = re * c - im * s;
    qr[base + 1] = re * s + im * c;
}

__global__ void rope_kr_kernel(float* __restrict__ kr,
                               const float* __restrict__ cs, const float* __restrict__ sn)
{
    int idx = blockIdx.x * blockDim.x + threadIdx.x;     // over B*T*32 pairs
    if (idx >= BB * TT * 32) return;
    int i  = idx & 31;
    int bt = idx >> 5;
    int t  = bt & (TT - 1);
    float c = cs[t * 32 + i], s = sn[t * 32 + i];
    size_t base = (size_t)bt * DHR_ + 2 * i;
    float re = kr[base], im = kr[base + 1];
    kr[base]     = re * c - im * s;
    kr[base + 1] = re * s + im * c;
}

// ---------------- fused flash-attention core ----------------
// Q[b,h,t,0:576] = [qlat | qr] (pre-scaled), K[b,s,0:576] = [ckv | kr], V = ckv.
// 64-query tiles, online softmax, ctx[b,h,t,0:512] output.
#define FPITCH 68
#define FSM_FLOATS (576*FPITCH + 64*FPITCH + 64*FPITCH + 64*17 + 4*64)

__global__ __launch_bounds__(256, 1) void flash_kernel(
    const float* __restrict__ qlat, const float* __restrict__ qr,
    const float* __restrict__ ckv,  const float* __restrict__ kr,
    float* __restrict__ ctx)
{
    extern __shared__ float sm[];
    float* Qs   = sm;                      // [576][68]  transposed: Qs[d][i]
    float* KVs  = Qs  + 576 * FPITCH;      // [64][68]
    float* Ps   = KVs + 64 * FPITCH;       // [64][68]
    float* Red  = Ps  + 64 * FPITCH;       // [64][17]
    float* msm  = Red + 64 * 17;
    float* lsm  = msm + 64;
    float* fsm  = lsm + 64;
    float* mnsm = fsm + 64;

    int qt = blockIdx.x, h = blockIdx.y, b = blockIdx.z;
    int t0 = qt * 64;
    int tid = threadIdx.x;
    int tx = tid & 15, ty = tid >> 4;
    const float scale = rsqrtf((float)(HS_ + DHR_));

    const float* qlatp = qlat + ((size_t)(b * NH_ + h) * TT + t0) * NLKV_;
    const float* qrp   = qr   + ((size_t)b * TT + t0) * (NH_ * DHR_) + h * DHR_;
    const float* ckvb  = ckv  + (size_t)b * TT * NLKV_;
    const float* krb   = kr   + (size_t)b * TT * DHR_;

    // load resident Q tile (transposed + scaled)
    for (int idx = tid; idx < 64 * 512; idx += 256) {
        int i = idx >> 9, d = idx & 511;
        Qs[d * FPITCH + i] = qlatp[(size_t)i * NLKV_ + d] * scale;
    }
    for (int idx = tid; idx < 64 * 64; idx += 256) {
        int i = idx >> 6, d = idx & 63;
        Qs[(512 + d) * FPITCH + i] = qrp[(size_t)i * (NH_ * DHR_) + d] * scale;
    }
    if (tid < 64) { msm[tid] = -1e30f; lsm[tid] = 0.f; }
    __syncthreads();

    float acc[4][8][4];
#pragma unroll
    for (int i = 0; i < 4; i++)
#pragma unroll
        for (int g = 0; g < 8; g++)
#pragma unroll
            for (int v = 0; v < 4; v++) acc[i][g][v] = 0.f;

    for (int kt = 0; kt <= qt; kt++) {
        int s0 = kt * 64;
        float S[4][4];
#pragma unroll
        for (int i = 0; i < 4; i++)
#pragma unroll
            for (int j = 0; j < 4; j++) S[i][j] = 0.f;

        // ---- scores: 9 d-chunks of 64 ----
        for (int dc = 0; dc < 9; dc++) {
            __syncthreads();
            {   // load K chunk transposed: KVs[d][j]
                int j = tid >> 2;
                int dbase = (tid & 3) * 16;
                const float* src = (dc < 8)
                    ? (ckvb + (size_t)(s0 + j) * NLKV_ + dc * 64 + dbase)
                    : (krb  + (size_t)(s0 + j) * DHR_ + dbase);
#pragma unroll
                for (int u = 0; u < 16; u += 4) {
                    float4 v = *(const float4*)(src + u);
                    KVs[(dbase + u + 0) * FPITCH + j] = v.x;
                    KVs[(dbase + u + 1) * FPITCH + j] = v.y;
                    KVs[(dbase + u + 2) * FPITCH + j] = v.z;
                    KVs[(dbase + u + 3) * FPITCH + j] = v.w;
                }
            }
            __syncthreads();
            const float* Qc = Qs + dc * 64 * FPITCH;
#pragma unroll 8
            for (int d = 0; d < 64; d++) {
                float4 qv = *(const float4*)(Qc  + d * FPITCH + (ty << 2));
                float4 kv = *(const float4*)(KVs + d * FPITCH + (tx << 2));
                float qa[4] = {qv.x, qv.y, qv.z, qv.w};
                float ka[4] = {kv.x, kv.y, kv.z, kv.w};
#pragma unroll
                for (int ii = 0; ii < 4; ii++)
#pragma unroll
                    for (int jj = 0; jj < 4; jj++)
                        S[ii][jj] = fmaf(qa[ii], ka[jj], S[ii][jj]);
            }
        }

        // causal mask on diagonal tile
        if (kt == qt) {
#pragma unroll
            for (int ii = 0; ii < 4; ii++)
#pragma unroll
                for (int jj = 0; jj < 4; jj++)
                    if ((tx << 2) + jj > (ty << 2) + ii) S[ii][jj] = -1e30f;
        }

        // ---- online softmax ----
#pragma unroll
        for (int ii = 0; ii < 4; ii++) {
            float mx = fmaxf(fmaxf(S[ii][0], S[ii][1]), fmaxf(S[ii][2], S[ii][3]));
            Red[((ty << 2) + ii) * 17 + tx] = mx;
        }
        __syncthreads();
        if (tid < 64) {
            float mx = -1e30f;
#pragma unroll
            for (int u = 0; u < 16; u++) mx = fmaxf(mx, Red[tid * 17 + u]);
            float mo = msm[tid];
            float mn = fmaxf(mo, mx);
            msm[tid]  = mn;
            mnsm[tid] = mn;
            fsm[tid]  = __expf(mo - mn);
        }
        __syncthreads();
#pragma unroll
        for (int ii = 0; ii < 4; ii++) {
            int i = (ty << 2) + ii;
            float mn = mnsm[i];
            float f  = fsm[i];
            float4 p;
            p.x = __expf(S[ii][0] - mn);
            p.y = __expf(S[ii][1] - mn);
            p.z = __expf(S[ii][2] - mn);
            p.w = __expf(S[ii][3] - mn);
            *(float4*)(Ps + i * FPITCH + (tx << 2)) = p;
            Red[i * 17 + tx] = p.x + p.y + p.z + p.w;
#pragma unroll
            for (int g = 0; g < 8; g++)
#pragma unroll
                for (int vv = 0; vv < 4; vv++) acc[ii][g][vv] *= f;
        }
        __syncthreads();
        if (tid < 64) {
            float sum = 0.f;
#pragma unroll
            for (int u = 0; u < 16; u++) sum += Red[tid * 17 + u];
            lsm[tid] = lsm[tid] * fsm[tid] + sum;
        }

        // ---- PV: 8 v-chunks of 64 ----
#pragma unroll
        for (int g = 0; g < 8; g++) {
            __syncthreads();
            {   // load V chunk (natural layout): KVs[j][v]
                int j = tid >> 2;
                int vbase = (tid & 3) * 16;
                const float* src = ckvb + (size_t)(s0 + j) * NLKV_ + g * 64 + vbase;
                float* dst = KVs + j * FPITCH + vbase;
#pragma unroll
                for (int u = 0; u < 16; u += 4)
                    *(float4*)(dst + u) = *(const float4*)(src + u);
            }
            __syncthreads();
#pragma unroll 4
            for (int j = 0; j < 64; j++) {
                float pr[4];
#pragma unroll
                for (int ii = 0; ii < 4; ii++) pr[ii] = Ps[((ty << 2) + ii) * FPITCH + j];
                float4 v = *(const float4*)(KVs + j * FPITCH + (tx << 2));
                float va[4] = {v.x, v.y, v.z, v.w};
#pragma unroll
                for (int ii = 0; ii < 4; ii++)
#pragma unroll
                    for (int vv = 0; vv < 4; vv++)
                        acc[ii][g][vv] = fmaf(pr[ii], va[vv], acc[ii][g][vv]);
            }
        }
    }

    // ---- write ctx ----
#pragma unroll
    for (int ii = 0; ii < 4; ii++) {
        int i = (ty << 2) + ii;
        float inv = 1.0f / lsm[i];
        float* orow = ctx + ((size_t)(b * NH_ + h) * TT + t0 + i) * NLKV_;
#pragma unroll
        for (int g = 0; g < 8; g++) {
            float4 o;
            o.x = acc[ii][g][0] * inv;
            o.y = acc[ii][g][1] * inv;
            o.z = acc[ii][g][2] * inv;
            o.w = acc[ii][g][3] * inv;
            *(float4*)(orow + g * 64 + (tx << 2)) = o;
        }
    }
}

// ---------------- launch ----------------
extern "C" void kernel_launch(void* const* d_in, const int* in_sizes, int n_in,
                              void* d_out, int out_size)
{
    (void)in_sizes; (void)n_in; (void)out_size;
    const float* x    = (const float*)d_in[0];
    const float* cs   = (const float*)d_in[1];
    const float* sn   = (const float*)d_in[2];
    const float* W_dq = (const float*)d_in[3];
    const float* W_uq = (const float*)d_in[4];
    const float* W_dkv= (const float*)d_in[5];
    const float* W_uk = (const float*)d_in[6];
    const float* W_uv = (const float*)d_in[7];
    const float* W_qr = (const float*)d_in[8];
    const float* W_kr = (const float*)d_in[9];
    const float* W_o  = (const float*)d_in[10];
    float* y = (float*)d_out;

    float *cq, *ckv, *keff, *vtmp, *qlat, *qr, *kr, *ctx;
    cudaGetSymbolAddress((void**)&cq,   d_cq);
    cudaGetSymbolAddress((void**)&ckv,  d_ckv);
    cudaGetSymbolAddress((void**)&keff, d_keff);
    cudaGetSymbolAddress((void**)&vtmp, d_vtmp);
    cudaGetSymbolAddress((void**)&qlat, d_qlat);
    cudaGetSymbolAddress((void**)&qr,   d_qr);
    cudaGetSymbolAddress((void**)&kr,   d_kr);
    cudaGetSymbolAddress((void**)&ctx,  d_ctx);

    const int MT = BB * TT;   // 4096

    // 1) c_q = x @ W_dq^T          (4096 x 512, K=2048)
    sgemm_g<<<dim3(NLQ_/64, MT/64, 1), 256>>>(x, W_dq, cq,
        MT, NLQ_, CC,  CC,1, 0,0,  CC,1, 0,0,  NLQ_, 0,0, 1);

    // 2) c_kv = x @ W_dkv^T        (4096 x 512, K=2048)
    sgemm_g<<<dim3(NLKV_/64, MT/64, 1), 256>>>(x, W_dkv, ckv,
        MT, NLKV_, CC,  CC,1, 0,0,  CC,1, 0,0,  NLKV_, 0,0, 1);

    // 3) k_eff[h,q,k] = sum_s Wuq[q*2048+h*128+s] * Wuk[h*65536+s*512+k]  (16 x 512x512, K=128)
    sgemm_g<<<dim3(NLKV_/64, NLQ_/64, NH_), 256>>>(W_uq, W_uk, keff,
        NLQ_, NLKV_, HS_,
        CC,1, 0,(long long)HS_,
        1,(long long)NLKV_, 0,(long long)HS_*NLKV_,
        NLKV_, 0,(long long)NLQ_*NLKV_, NH_);

    // 4) v_tmp[k,d] = sum_c W_uv[c,k] * W_o[d,c]   (512 x 2048, K=2048)
    sgemm_g<<<dim3(CC/64, NLKV_/64, 1), 256>>>(W_uv, W_o, vtmp,
        NLKV_, CC, CC,
        1,(long long)NLKV_, 0,0,
        CC,1, 0,0,
        CC, 0,0, 1);

    // 5) qr_lin = c_q @ W_qr^T     (4096 x 1024, K=512)
    sgemm_g<<<dim3((NH_*DHR_)/64, MT/64, 1), 256>>>(cq, W_qr, qr,
        MT, NH_*DHR_, NLQ_,  NLQ_,1, 0,0,  NLQ_,1, 0,0,  NH_*DHR_, 0,0, 1);

    // 6) kr_lin = x @ W_kr^T       (4096 x 64, K=2048)
    sgemm_g<<<dim3(1, MT/64, 1), 256>>>(x, W_kr, kr,
        MT, DHR_, CC,  CC,1, 0,0,  CC,1, 0,0,  DHR_, 0,0, 1);

    // 7) RoPE (in place)
    rope_qr_kernel<<<(BB*TT*NH_*32 + 255)/256, 256>>>(qr, cs, sn);
    rope_kr_kernel<<<(BB*TT*32 + 255)/256, 256>>>(kr, cs, sn);

    // 8) q_lat[b,h,t,k] = sum_q c_q[b,t,q] * k_eff[h,q,k]   (32 x 2048x512, K=512)
    sgemm_g<<<dim3(NLKV_/64, TT/64, BB*NH_), 256>>>(cq, keff, qlat,
        TT, NLKV_, NLQ_,
        NLQ_,1, (long long)TT*NLQ_, 0,
        1,(long long)NLKV_, 0,(long long)NLQ_*NLKV_,
        NLKV_, (long long)NH_*TT*NLKV_, (long long)TT*NLKV_, NH_);

    // 9) flash attention core -> ctx
    static const size_t smem_bytes = (size_t)FSM_FLOATS * sizeof(float);
    cudaFuncSetAttribute(flash_kernel, cudaFuncAttributeMaxDynamicSharedMemorySize,
                         (int)smem_bytes);
    flash_kernel<<<dim3(TT/64, NH_, BB), 256, smem_bytes>>>(qlat, qr, ckv, kr, ctx);

    // 10) y[b,t,h*128+d] = sum_k ctx[b,h,t,k] * v_tmp[k, h*128+d]  (32 x 2048x128, K=512)
    sgemm_g<<<dim3(HS_/64, TT/64, BB*NH_), 256>>>(ctx, vtmp, y,
        TT, HS_, NLKV_,
        NLKV_,1, (long long)NH_*TT*NLKV_, (long long)TT*NLKV_,
        1,(long long)CC, 0,(long long)HS_,
        CC, (long long)TT*CC, (long long)HS_, NH_);
}